// round 12
// baseline (speedup 1.0000x reference)
#include <cuda_runtime.h>

// Problem constants
#define BB   256
#define TTOT 16384
#define ALPHA_F 0.95f

// LIF chunking (verified exact): 64 chunks of 256, warm-up 512
#define LCHUNK 256
#define WARM   512
#define NCHUNK (TTOT / TTOT)  /* unused */
#define NCH    64             // number of chunks

// lif smem tiling: tile = [3ch][32 t][64 b pad 65]
#define TTILE 32
#define BPAD  65
#define CHSZ  (TTILE * BPAD)            // 2080 floats
#define UBUF  (3 * CHSZ)                // 6240 floats = 24960 B
#define MROWS 192                       // 3ch * 64b mask words per tile
#define LIF_SMEM_BYTES (2 * UBUF * 4 + 2 * MROWS * 4)   // 51456 B

// ---------------------------------------------------------------------------
// Kernel 1: causal conv (measured ~21.6us).
// ---------------------------------------------------------------------------
__global__ __launch_bounds__(512) void conv_kernel(
    const float* __restrict__ x,
    const float* __restrict__ w0,
    const float* __restrict__ w1,
    const float* __restrict__ w2,
    float* __restrict__ u)
{
    __shared__ float xs[2080];

    const int b    = blockIdx.x;
    const int tile = blockIdx.y;
    const int t0   = tile * 2048;
    const float* xb = x + (size_t)b * TTOT;

    for (int i = threadIdx.x; i < 2080; i += 512) {
        int gi = t0 + i - 31;
        xs[i] = (gi >= 0 && gi < TTOT) ? xb[gi] : 0.0f;
    }

    float W2[32], W1[16], W0[8];
#pragma unroll
    for (int i = 0; i < 32; i++) W2[i] = w2[i] * 0.1767766952966369f;
#pragma unroll
    for (int i = 0; i < 16; i++) W1[i] = w1[i] * 0.25f;
#pragma unroll
    for (int i = 0; i < 8;  i++) W0[i] = w0[i] * 0.3535533905932738f;

    __syncthreads();

    const int tt0 = threadIdx.x * 4;

    float xv[36];
#pragma unroll
    for (int q = 0; q < 9; q++) {
        float4 v = *reinterpret_cast<const float4*>(&xs[tt0 + 4 * q]);
        xv[4 * q + 0] = v.x; xv[4 * q + 1] = v.y;
        xv[4 * q + 2] = v.z; xv[4 * q + 3] = v.w;
    }

    float a0[4] = {0.f, 0.f, 0.f, 0.f};
    float a1[4] = {0.f, 0.f, 0.f, 0.f};
    float a2[4] = {0.f, 0.f, 0.f, 0.f};

#pragma unroll
    for (int kk = 0; kk < 32; kk++)
#pragma unroll
        for (int r = 0; r < 4; r++)
            a2[r] = fmaf(W2[kk], xv[kk + r], a2[r]);
#pragma unroll
    for (int kk = 0; kk < 16; kk++)
#pragma unroll
        for (int r = 0; r < 4; r++)
            a1[r] = fmaf(W1[kk], xv[16 + kk + r], a1[r]);
#pragma unroll
    for (int kk = 0; kk < 8; kk++)
#pragma unroll
        for (int r = 0; r < 4; r++)
            a0[r] = fmaf(W0[kk], xv[24 + kk + r], a0[r]);

    const int t = t0 + tt0;
    float* ub = u + (size_t)b * 3 * TTOT;
    *reinterpret_cast<float4*>(ub + 0 * TTOT + t) = make_float4(a0[0], a0[1], a0[2], a0[3]);
    *reinterpret_cast<float4*>(ub + 1 * TTOT + t) = make_float4(a1[0], a1[1], a1[2], a1[3]);
    *reinterpret_cast<float4*>(ub + 2 * TTOT + t) = make_float4(a2[0], a2[1], a2[2], a2[3]);
}

// ---------------------------------------------------------------------------
// Kernel 2: LIF + WTA scan, warp-specialized, bitmask spikes.
// Block = 128 thr: warps 0-1 consumers (64 batches), warps 2-3 producers.
// Grid = 256 = (chunk 0..63) x (batch quarter) -> 2 independent blocks/SM.
// ---------------------------------------------------------------------------
__global__ __launch_bounds__(128) void lif_kernel(
    const float* __restrict__ u,
    float* __restrict__ s)
{
    extern __shared__ float sm[];
    float*    ubuf[2] = { sm, sm + UBUF };
    unsigned* mbuf[2] = { reinterpret_cast<unsigned*>(sm + 2 * UBUF),
                          reinterpret_cast<unsigned*>(sm + 2 * UBUF) + MROWS };

    const int tid   = threadIdx.x;
    const int c     = (int)blockIdx.x >> 2;
    const int bbase = ((int)blockIdx.x & 3) << 6;

    const int commit = c * LCHUNK;
    int start = commit - WARM; if (start < 0) start = 0;
    const int ntiles    = (commit + LCHUNK - start) >> 5;   // 8..24
    const int commit_i0 = (commit - start) >> 5;

    const bool is_prod = (tid >= 64);
    const int  ptid    = tid & 63;    // role-local id 0..63

    // staging map: tile = 192 rows (64b x 3ch) x 8 float4 = 1536 chunks,
    // 24 per producer thread. idx = (h*12+j)*64 + ptid ; o=idx&7 ; row=idx>>3 ;
    // ch = row>>6 ; br = row&63.
#define LD_BATCH(t0v, h, pf)                                                   \
    {                                                                          \
        _Pragma("unroll")                                                      \
        for (int j = 0; j < 12; j++) {                                         \
            int idx = ((h) * 12 + j) * 64 + ptid;                              \
            int o   = idx & 7;                                                 \
            int row = idx >> 3;                                                \
            int ch  = row >> 6;                                                \
            int br  = row & 63;                                                \
            const float* g = u + ((size_t)((bbase + br) * 3 + ch)) * TTOT      \
                               + (t0v) + 4 * o;                                \
            pf[j] = *reinterpret_cast<const float4*>(g);                       \
        }                                                                      \
    }
#define ST_BATCH(dst, h, pf)                                                   \
    {                                                                          \
        _Pragma("unroll")                                                      \
        for (int j = 0; j < 12; j++) {                                         \
            int idx = ((h) * 12 + j) * 64 + ptid;                              \
            int o   = idx & 7;                                                 \
            int row = idx >> 3;                                                \
            int ch  = row >> 6;                                                \
            int br  = row & 63;                                                \
            float* p = (dst) + ch * CHSZ + (4 * o) * BPAD + br;                \
            p[0 * BPAD] = pf[j].x;                                             \
            p[1 * BPAD] = pf[j].y;                                             \
            p[2 * BPAD] = pf[j].z;                                             \
            p[3 * BPAD] = pf[j].w;                                             \
        }                                                                      \
    }
    // mask drain: 192 rows x 8 float4 = 1536, 24 per thread, same map.
#define DRAIN_MASKS(mb, t0v)                                                   \
    {                                                                          \
        _Pragma("unroll")                                                      \
        for (int q = 0; q < 24; q++) {                                         \
            int idx = q * 64 + ptid;                                           \
            int o   = idx & 7;                                                 \
            int row = idx >> 3;                                                \
            int ch  = row >> 6;                                                \
            int br  = row & 63;                                                \
            unsigned m = (mb)[row] >> (4 * o);                                 \
            float4 v;                                                          \
            v.x = (m & 1u) ? 1.0f : 0.0f;                                      \
            v.y = (m & 2u) ? 1.0f : 0.0f;                                      \
            v.z = (m & 4u) ? 1.0f : 0.0f;                                      \
            v.w = (m & 8u) ? 1.0f : 0.0f;                                      \
            float* g = s + ((size_t)((bbase + br) * 3 + ch)) * TTOT            \
                         + (t0v) + 4 * o;                                      \
            *reinterpret_cast<float4*>(g) = v;                                 \
        }                                                                      \
    }

    // prime tile 0
    if (is_prod) {
        float4 pa[12], pb[12];
        LD_BATCH(start, 0, pa);
        LD_BATCH(start, 1, pb);
        ST_BATCH(ubuf[0], 0, pa);
        ST_BATCH(ubuf[0], 1, pb);
    }
    __syncthreads();

    float y0 = 0.f, y1 = 0.f, y2 = 0.f;

    for (int i = 0; i < ntiles; i++) {
        const int t0 = start + i * TTILE;

        if (!is_prod) {
            // -------- consumer: pure scan of tile i (scalar LDS, no STS) ----
            const float* Pc = ubuf[i & 1] + ptid;
            if (i >= commit_i0) {
                unsigned m0 = 0u, m1 = 0u, m2 = 0u;
#pragma unroll
                for (int t = 0; t < TTILE; t++) {
                    const float u0 = Pc[0 * CHSZ + t * BPAD];
                    const float u1 = Pc[1 * CHSZ + t * BPAD];
                    const float u2 = Pc[2 * CHSZ + t * BPAD];
                    const float w0v = fmaf(ALPHA_F, y0, u0);
                    const float w1v = fmaf(ALPHA_F, y1, u1);
                    const float w2v = fmaf(ALPHA_F, y2, u2);
                    const bool g01 = (w0v >= w1v), g02 = (w0v >= w2v), g12 = (w1v >= w2v);
                    const bool f0 = g01 & g02 & (w0v >= 1.0f);
                    const bool f1 = (!g01) & g12 & (w1v >= 1.0f);
                    const bool f2 = (!g02) & (!g12) & (w2v >= 1.0f);
                    y0 = w0v - (f0 ? 1.0f : 0.0f);
                    y1 = w1v - (f1 ? 1.0f : 0.0f);
                    y2 = w2v - (f2 ? 1.0f : 0.0f);
                    m0 |= f0 ? (1u << t) : 0u;
                    m1 |= f1 ? (1u << t) : 0u;
                    m2 |= f2 ? (1u << t) : 0u;
                }
                unsigned* mb = mbuf[i & 1];
                mb[0 * 64 + ptid] = m0;
                mb[1 * 64 + ptid] = m1;
                mb[2 * 64 + ptid] = m2;
            } else {
#pragma unroll
                for (int t = 0; t < TTILE; t++) {
                    const float u0 = Pc[0 * CHSZ + t * BPAD];
                    const float u1 = Pc[1 * CHSZ + t * BPAD];
                    const float u2 = Pc[2 * CHSZ + t * BPAD];
                    const float w0v = fmaf(ALPHA_F, y0, u0);
                    const float w1v = fmaf(ALPHA_F, y1, u1);
                    const float w2v = fmaf(ALPHA_F, y2, u2);
                    const bool g01 = (w0v >= w1v), g02 = (w0v >= w2v), g12 = (w1v >= w2v);
                    const bool f0 = g01 & g02 & (w0v >= 1.0f);
                    const bool f1 = (!g01) & g12 & (w1v >= 1.0f);
                    const bool f2 = (!g02) & (!g12) & (w2v >= 1.0f);
                    y0 = w0v - (f0 ? 1.0f : 0.0f);
                    y1 = w1v - (f1 ? 1.0f : 0.0f);
                    y2 = w2v - (f2 ? 1.0f : 0.0f);
                }
            }
        } else {
            // -------- producer: stage tile i+1, drain masks of tile i-1 -----
            if (i + 1 < ntiles) {
                float4 pa[12], pb[12];
                LD_BATCH(t0 + TTILE, 0, pa);
                LD_BATCH(t0 + TTILE, 1, pb);
                if (i >= 1 && i - 1 >= commit_i0)
                    DRAIN_MASKS(mbuf[(i - 1) & 1], t0 - TTILE);  // overlaps LDG flight
                ST_BATCH(ubuf[(i + 1) & 1], 0, pa);
                ST_BATCH(ubuf[(i + 1) & 1], 1, pb);
            } else {
                if (i >= 1 && i - 1 >= commit_i0)
                    DRAIN_MASKS(mbuf[(i - 1) & 1], t0 - TTILE);
            }
        }

        __syncthreads();
    }

    // epilogue: drain last commit tile's masks
    if (is_prod) {
        const int ilast = ntiles - 1;
        DRAIN_MASKS(mbuf[ilast & 1], start + ilast * TTILE);
    }
#undef LD_BATCH
#undef ST_BATCH
#undef DRAIN_MASKS
}

// ---------------------------------------------------------------------------
// Launch.
// ---------------------------------------------------------------------------
extern "C" void kernel_launch(void* const* d_in, const int* in_sizes, int n_in,
                              void* d_out, int out_size)
{
    const float* x  = (const float*)d_in[0];
    const float* w0 = (const float*)d_in[1];
    const float* w1 = (const float*)d_in[2];
    const float* w2 = (const float*)d_in[3];

    float* u = (float*)d_out;
    float* s = u + (size_t)BB * 3 * TTOT;

    cudaFuncSetAttribute(lif_kernel, cudaFuncAttributeMaxDynamicSharedMemorySize,
                         LIF_SMEM_BYTES);

    dim3 cgrid(BB, TTOT / 2048);
    conv_kernel<<<cgrid, 512>>>(x, w0, w1, w2, u);

    lif_kernel<<<NCH * 4, 128, LIF_SMEM_BYTES>>>(u, s);
}

// round 13
// speedup vs baseline: 1.2431x; 1.2431x over previous
#include <cuda_runtime.h>

// Problem constants
#define BB   256
#define TTOT 16384
#define ALPHA_F 0.95f

// LIF chunking (verified exact): 64 chunks of 256, warm-up 512
#define LCHUNK 256
#define WARM   512
#define NCH    64

// lif smem: tile rows r = br*3+ch (br 0..31), 36 words (144B) per row.
#define TTILE 32
#define ROWW  36
#define NROW  96                        // 32 b x 3 ch
#define UBUF  (NROW * ROWW)             // 3456 floats = 13824 B

// ---------------------------------------------------------------------------
// Kernel 1: causal conv (measured ~21.6us).
// ---------------------------------------------------------------------------
__global__ __launch_bounds__(512) void conv_kernel(
    const float* __restrict__ x,
    const float* __restrict__ w0,
    const float* __restrict__ w1,
    const float* __restrict__ w2,
    float* __restrict__ u)
{
    __shared__ float xs[2080];

    const int b    = blockIdx.x;
    const int tile = blockIdx.y;
    const int t0   = tile * 2048;
    const float* xb = x + (size_t)b * TTOT;

    for (int i = threadIdx.x; i < 2080; i += 512) {
        int gi = t0 + i - 31;
        xs[i] = (gi >= 0 && gi < TTOT) ? xb[gi] : 0.0f;
    }

    float W2[32], W1[16], W0[8];
#pragma unroll
    for (int i = 0; i < 32; i++) W2[i] = w2[i] * 0.1767766952966369f;
#pragma unroll
    for (int i = 0; i < 16; i++) W1[i] = w1[i] * 0.25f;
#pragma unroll
    for (int i = 0; i < 8;  i++) W0[i] = w0[i] * 0.3535533905932738f;

    __syncthreads();

    const int tt0 = threadIdx.x * 4;

    float xv[36];
#pragma unroll
    for (int q = 0; q < 9; q++) {
        float4 v = *reinterpret_cast<const float4*>(&xs[tt0 + 4 * q]);
        xv[4 * q + 0] = v.x; xv[4 * q + 1] = v.y;
        xv[4 * q + 2] = v.z; xv[4 * q + 3] = v.w;
    }

    float a0[4] = {0.f, 0.f, 0.f, 0.f};
    float a1[4] = {0.f, 0.f, 0.f, 0.f};
    float a2[4] = {0.f, 0.f, 0.f, 0.f};

#pragma unroll
    for (int kk = 0; kk < 32; kk++)
#pragma unroll
        for (int r = 0; r < 4; r++)
            a2[r] = fmaf(W2[kk], xv[kk + r], a2[r]);
#pragma unroll
    for (int kk = 0; kk < 16; kk++)
#pragma unroll
        for (int r = 0; r < 4; r++)
            a1[r] = fmaf(W1[kk], xv[16 + kk + r], a1[r]);
#pragma unroll
    for (int kk = 0; kk < 8; kk++)
#pragma unroll
        for (int r = 0; r < 4; r++)
            a0[r] = fmaf(W0[kk], xv[24 + kk + r], a0[r]);

    const int t = t0 + tt0;
    float* ub = u + (size_t)b * 3 * TTOT;
    *reinterpret_cast<float4*>(ub + 0 * TTOT + t) = make_float4(a0[0], a0[1], a0[2], a0[3]);
    *reinterpret_cast<float4*>(ub + 1 * TTOT + t) = make_float4(a1[0], a1[1], a1[2], a1[3]);
    *reinterpret_cast<float4*>(ub + 2 * TTOT + t) = make_float4(a2[0], a2[1], a2[2], a2[3]);
}

// ---------------------------------------------------------------------------
// Kernel 2: LIF + WTA scan. Block = ONE warp = 32 batches of one chunk.
// Grid = 512 = (chunk 0..63) x (batch eighth). The warp stages its own tiles
// via cp.async.cg (no producer warps, no __syncthreads), scans via LDS.128,
// accumulates spike bitmasks in registers, drains them coalesced.
// ---------------------------------------------------------------------------
__global__ __launch_bounds__(32) void lif_kernel(
    const float* __restrict__ u,
    float* __restrict__ s)
{
    __shared__ float    ub2[2][UBUF];
    __shared__ unsigned mb[NROW];

    const int tid   = threadIdx.x;           // 0..31
    const int c     = (int)blockIdx.x >> 3;  // chunk
    const int bbase = ((int)blockIdx.x & 7) << 5;

    const int commit = c * LCHUNK;
    int start = commit - WARM; if (start < 0) start = 0;
    const int ntiles = (commit + LCHUNK - start) >> 5;   // 8..24
    const int ci0    = (commit - start) >> 5;

    // staging geometry: thread owns (p8 = tid>>3, o = tid&7); covers rows
    // r = 4j + p8 (j = 0..23) at t-slot 4o. Warp op = rows 0..3 x 128B lines.
    const int p8 = tid >> 3;
    const int o  = tid & 7;
    const float* gsrc = u + (size_t)(bbase * 3 + p8) * TTOT + 4 * o;
    float*       gdst = s + (size_t)(bbase * 3) * TTOT;        // + row*TTOT later

    unsigned sb[2];
    sb[0] = (unsigned)__cvta_generic_to_shared(&ub2[0][0]) + 144 * p8 + 16 * o;
    sb[1] = (unsigned)__cvta_generic_to_shared(&ub2[1][0]) + 144 * p8 + 16 * o;

#define STAGE(bi, tv)                                                          \
    {                                                                          \
        const unsigned sbb = sb[bi];                                           \
        _Pragma("unroll")                                                      \
        for (int j = 0; j < 24; j++) {                                         \
            const float* gp = gsrc + (size_t)(4 * j) * TTOT + (tv);            \
            asm volatile("cp.async.cg.shared.global [%0], [%1], 16;"           \
                         :: "r"(sbb + 576u * j), "l"(gp) : "memory");          \
        }                                                                      \
        asm volatile("cp.async.commit_group;" ::: "memory");                   \
    }

#define C_STEP(uu0, uu1, uu2, MASKOP)                                          \
    {                                                                          \
        const float w0v = fmaf(ALPHA_F, y0, (uu0));                            \
        const float w1v = fmaf(ALPHA_F, y1, (uu1));                            \
        const float w2v = fmaf(ALPHA_F, y2, (uu2));                            \
        const bool g01 = (w0v >= w1v), g02 = (w0v >= w2v), g12 = (w1v >= w2v); \
        const bool f0 = g01 & g02 & (w0v >= 1.0f);                             \
        const bool f1 = (!g01) & g12 & (w1v >= 1.0f);                          \
        const bool f2 = (!g02) & (!g12) & (w2v >= 1.0f);                       \
        y0 = f0 ? (w0v - 1.0f) : w0v;                                          \
        y1 = f1 ? (w1v - 1.0f) : w1v;                                          \
        y2 = f2 ? (w2v - 1.0f) : w2v;                                          \
        MASKOP                                                                 \
    }

    // prime tile 0
    STAGE(0, start);

    float y0 = 0.f, y1 = 0.f, y2 = 0.f;

    for (int i = 0; i < ntiles; i++) {
        const int t0 = start + i * TTILE;

        // tile i data ready
        asm volatile("cp.async.wait_group 0;" ::: "memory");
        __syncwarp();

        // stage tile i+1 (its buffer was last read at tile i-1; all lanes are
        // past that point after the syncwarp above). Lands during scan of i.
        if (i + 1 < ntiles) STAGE((i + 1) & 1, t0 + TTILE);

        // ---- scan tile i: rows 3*tid..3*tid+2, LDS.128 over 4 t at a time --
        const float* base = &ub2[i & 1][0] + tid * (3 * ROWW);
        const float4* q0 = reinterpret_cast<const float4*>(base);
        const float4* q1 = reinterpret_cast<const float4*>(base + ROWW);
        const float4* q2 = reinterpret_cast<const float4*>(base + 2 * ROWW);

        if (i >= ci0) {
            unsigned m0 = 0u, m1 = 0u, m2 = 0u;
#pragma unroll
            for (int g = 0; g < 8; g++) {
                const float4 a0v = q0[g];
                const float4 a1v = q1[g];
                const float4 a2v = q2[g];
                C_STEP(a0v.x, a1v.x, a2v.x,
                       { m0 |= f0 ? 1u << (4*g+0) : 0u; m1 |= f1 ? 1u << (4*g+0) : 0u; m2 |= f2 ? 1u << (4*g+0) : 0u; })
                C_STEP(a0v.y, a1v.y, a2v.y,
                       { m0 |= f0 ? 1u << (4*g+1) : 0u; m1 |= f1 ? 1u << (4*g+1) : 0u; m2 |= f2 ? 1u << (4*g+1) : 0u; })
                C_STEP(a0v.z, a1v.z, a2v.z,
                       { m0 |= f0 ? 1u << (4*g+2) : 0u; m1 |= f1 ? 1u << (4*g+2) : 0u; m2 |= f2 ? 1u << (4*g+2) : 0u; })
                C_STEP(a0v.w, a1v.w, a2v.w,
                       { m0 |= f0 ? 1u << (4*g+3) : 0u; m1 |= f1 ? 1u << (4*g+3) : 0u; m2 |= f2 ? 1u << (4*g+3) : 0u; })
            }
            // publish masks, then drain coalesced (same warp)
            mb[3 * tid + 0] = m0;
            mb[3 * tid + 1] = m1;
            mb[3 * tid + 2] = m2;
            __syncwarp();
#pragma unroll
            for (int q = 0; q < 24; q++) {
                const int idx = q * 32 + tid;
                const int o2  = idx & 7;
                const int row = idx >> 3;          // q*4 + tid>>3
                const unsigned m = mb[row] >> (4 * o2);
                float4 v;
                v.x = (m & 1u) ? 1.0f : 0.0f;
                v.y = (m & 2u) ? 1.0f : 0.0f;
                v.z = (m & 4u) ? 1.0f : 0.0f;
                v.w = (m & 8u) ? 1.0f : 0.0f;
                *reinterpret_cast<float4*>(gdst + (size_t)row * TTOT + t0 + 4 * o2) = v;
            }
            __syncwarp();   // mb reads done before next commit tile rewrites it
        } else {
#pragma unroll
            for (int g = 0; g < 8; g++) {
                const float4 a0v = q0[g];
                const float4 a1v = q1[g];
                const float4 a2v = q2[g];
                C_STEP(a0v.x, a1v.x, a2v.x, )
                C_STEP(a0v.y, a1v.y, a2v.y, )
                C_STEP(a0v.z, a1v.z, a2v.z, )
                C_STEP(a0v.w, a1v.w, a2v.w, )
            }
        }
    }
#undef STAGE
#undef C_STEP
}

// ---------------------------------------------------------------------------
// Launch.
// ---------------------------------------------------------------------------
extern "C" void kernel_launch(void* const* d_in, const int* in_sizes, int n_in,
                              void* d_out, int out_size)
{
    const float* x  = (const float*)d_in[0];
    const float* w0 = (const float*)d_in[1];
    const float* w1 = (const float*)d_in[2];
    const float* w2 = (const float*)d_in[3];

    float* u = (float*)d_out;
    float* s = u + (size_t)BB * 3 * TTOT;

    dim3 cgrid(BB, TTOT / 2048);
    conv_kernel<<<cgrid, 512>>>(x, w0, w1, w2, u);

    lif_kernel<<<NCH * 8, 32>>>(u, s);
}